// round 1
// baseline (speedup 1.0000x reference)
#include <cuda_runtime.h>
#include <cuda_bf16.h>

// Shapes: N=128, LX=512, D=32, K=63, C=K*D=2016
// Inputs (metadata order): X_int(128,512,32) mask_X(128,512,1) W1(32,63) b1(63)
//                          W2(63,63) b2(63) W3(63,2016) b3(2016) T_bias(1,63)
// Output: (128,63) fp32

#define N_BATCH 128
#define LX      512
#define DIN     32
#define KDIM    63
#define CDIM    2016
#define TL      64   // l-tile for phase 2

// Scratch: h2 activations, padded to 64 channels per token. 16.8 MB.
__device__ float g_h2[(size_t)N_BATCH * LX * 64];

// ---------------------------------------------------------------------------
// Phase 1: h2[t] = relu(relu(X[t] @ W1 + b1) @ W2 + b2), one thread per token.
// Weights live in smem; all lanes in a warp read the same weight -> broadcast.
// ---------------------------------------------------------------------------
__global__ __launch_bounds__(256) void ttcn_phase1(
    const float* __restrict__ X,
    const float* __restrict__ W1, const float* __restrict__ b1,
    const float* __restrict__ W2, const float* __restrict__ b2)
{
    __shared__ float w1s[DIN * KDIM];   // 2016
    __shared__ float w2s[KDIM * KDIM];  // 3969
    __shared__ float b1s[KDIM], b2s[KDIM];

    const int tid = threadIdx.x;
    for (int i = tid; i < DIN * KDIM; i += 256) w1s[i] = W1[i];
    for (int i = tid; i < KDIM * KDIM; i += 256) w2s[i] = W2[i];
    if (tid < KDIM) { b1s[tid] = b1[tid]; b2s[tid] = b2[tid]; }
    __syncthreads();

    const int t = blockIdx.x * 256 + tid;  // token id, 0..65535

    float x[DIN];
    const float4* xp = (const float4*)(X + (size_t)t * DIN);
#pragma unroll
    for (int i = 0; i < DIN / 4; i++) {
        float4 v = xp[i];
        x[4*i+0] = v.x; x[4*i+1] = v.y; x[4*i+2] = v.z; x[4*i+3] = v.w;
    }

    float h[KDIM];
#pragma unroll
    for (int c = 0; c < KDIM; c++) {
        float acc = b1s[c];
#pragma unroll
        for (int j = 0; j < DIN; j++) acc = fmaf(x[j], w1s[j * KDIM + c], acc);
        h[c] = fmaxf(acc, 0.0f);
    }

    float* o = g_h2 + (size_t)t * 64;
#pragma unroll
    for (int c = 0; c < KDIM; c++) {
        float acc = b2s[c];
#pragma unroll
        for (int j = 0; j < KDIM; j++) acc = fmaf(h[j], w2s[j * KDIM + c], acc);
        o[c] = fmaxf(acc, 0.0f);
    }
    o[63] = 0.0f;  // pad channel (w3r[63]=0 makes it inert)
}

// ---------------------------------------------------------------------------
// Phase 2: fused f = h2 @ W3 + b3, masked online softmax over l, and
// X-weighted pooling. CTA = (n, block of 8 k's) -> 256 channels, one channel
// per thread. W3 column in registers; h2/X/mask tiles in smem. Masked l are
// skipped (their softmax weight is exactly 0 in fp32, matching reference).
// ---------------------------------------------------------------------------
__global__ __launch_bounds__(256) void ttcn_phase2(
    const float* __restrict__ X, const float* __restrict__ mask,
    const float* __restrict__ W3, const float* __restrict__ b3,
    const float* __restrict__ Tb, float* __restrict__ out)
{
    const int n   = blockIdx.x;          // 0..127
    const int kb  = blockIdx.y;          // 0..7
    const int tid = threadIdx.x;
    const int d   = tid & 31;            // 0..31  (warp lanes = d)
    const int kk  = tid >> 5;            // 0..7   (warp = one k)
    const int k   = kb * 8 + kk;         // 0..63 (63 invalid in last block)
    const bool valid = (k < KDIM);
    const int c   = k * DIN + d;         // channel in [0, 2016)

    __shared__ float h2s[TL][64];        // 16 KB
    __shared__ float xs[TL][DIN];        // 8 KB
    __shared__ float ms[TL];

    // W3 column -> registers (coalesced across threads: consecutive c)
    float w3r[64];
#pragma unroll
    for (int j = 0; j < KDIM; j++) w3r[j] = valid ? W3[j * CDIM + c] : 0.0f;
    w3r[63] = 0.0f;
    const float b3v = valid ? b3[c] : 0.0f;

    float m = -1e30f, Z = 0.0f, S = 0.0f;

    const float4* h2base = (const float4*)(g_h2 + (size_t)n * LX * 64);
    const float4* xbase  = (const float4*)(X + (size_t)n * LX * DIN);
    const float*  mbase  = mask + (size_t)n * LX;

    for (int l0 = 0; l0 < LX; l0 += TL) {
        __syncthreads();
        // stage h2 tile: TL*64 floats = 1024 float4
        float4* dh = (float4*)&h2s[0][0];
#pragma unroll
        for (int i = 0; i < (TL * 16) / 256; i++)
            dh[tid + 256 * i] = h2base[l0 * 16 + tid + 256 * i];
        // stage X tile: TL*32 floats = 512 float4
        float4* dx = (float4*)&xs[0][0];
#pragma unroll
        for (int i = 0; i < (TL * 8) / 256; i++)
            dx[tid + 256 * i] = xbase[l0 * 8 + tid + 256 * i];
        if (tid < TL) ms[tid] = mbase[l0 + tid];
        __syncthreads();

#pragma unroll 4
        for (int ll = 0; ll < TL; ll++) {
            if (ms[ll] == 0.0f) continue;  // warp-uniform skip; weight is 0
            float f0 = 0.f, f1 = 0.f, f2 = 0.f, f3 = 0.f;
#pragma unroll
            for (int jj = 0; jj < 16; jj++) {
                float4 h4 = *(const float4*)&h2s[ll][jj * 4];  // LDS.128 bcast
                f0 = fmaf(h4.x, w3r[4 * jj + 0], f0);
                f1 = fmaf(h4.y, w3r[4 * jj + 1], f1);
                f2 = fmaf(h4.z, w3r[4 * jj + 2], f2);
                f3 = fmaf(h4.w, w3r[4 * jj + 3], f3);
            }
            const float f  = b3v + (f0 + f1) + (f2 + f3);
            const float mn = fmaxf(m, f);
            const float c0 = __expf(m - mn);   // ==0 on first hit (m=-1e30)
            const float e  = __expf(f - mn);
            Z = fmaf(Z, c0, e);
            S = fmaf(S, c0, xs[ll][d] * e);
            m = mn;
        }
    }

    // out[n,k] = relu(sum_d S_d/Z_d + T_bias[k]); warp = one k
    float val = (valid && Z > 0.0f) ? (S / Z) : 0.0f;
#pragma unroll
    for (int off = 16; off; off >>= 1)
        val += __shfl_xor_sync(0xffffffffu, val, off);
    if (valid && (tid & 31) == 0)
        out[n * KDIM + k] = fmaxf(val + Tb[k], 0.0f);
}

extern "C" void kernel_launch(void* const* d_in, const int* in_sizes, int n_in,
                              void* d_out, int out_size) {
    const float* X    = (const float*)d_in[0];
    const float* mask = (const float*)d_in[1];
    const float* W1   = (const float*)d_in[2];
    const float* b1   = (const float*)d_in[3];
    const float* W2   = (const float*)d_in[4];
    const float* b2   = (const float*)d_in[5];
    const float* W3   = (const float*)d_in[6];
    const float* b3   = (const float*)d_in[7];
    const float* Tb   = (const float*)d_in[8];
    float* out = (float*)d_out;

    ttcn_phase1<<<(N_BATCH * LX) / 256, 256>>>(X, W1, b1, W2, b2);
    ttcn_phase2<<<dim3(N_BATCH, 8), 256>>>(X, mask, W3, b3, Tb, out);
}

// round 2
// speedup vs baseline: 1.3848x; 1.3848x over previous
#include <cuda_runtime.h>
#include <cuda_bf16.h>

// Shapes: N=128, LX=512, D=32, K=63, C=K*D=2016
// Inputs: X_int(128,512,32) mask_X(128,512,1) W1(32,63) b1(63)
//         W2(63,63) b2(63) W3(63,2016) b3(2016) T_bias(1,63)
// Output: (128,63) fp32

#define N_BATCH 128
#define LX      512
#define DIN     32
#define KDIM    63
#define CDIM    2016
#define TL      64

typedef unsigned long long u64;

// Scratch: h2 activations padded to 64 ch/token (pad ch = 0). 16.8 MB.
__device__ __align__(16) float g_h2[(size_t)N_BATCH * LX * 64];

// ---- f32x2 helpers (Blackwell packed fp32) --------------------------------
__device__ __forceinline__ u64 f2pack(float lo, float hi) {
    u64 r; asm("mov.b64 %0, {%1, %2};" : "=l"(r) : "f"(lo), "f"(hi)); return r;
}
__device__ __forceinline__ void f2unpack(u64 v, float& lo, float& hi) {
    asm("mov.b64 {%0, %1}, %2;" : "=f"(lo), "=f"(hi) : "l"(v));
}
__device__ __forceinline__ u64 fma2(u64 a, u64 b, u64 c) {
    u64 d; asm("fma.rn.f32x2 %0, %1, %2, %3;" : "=l"(d) : "l"(a), "l"(b), "l"(c));
    return d;
}
__device__ __forceinline__ u64 add2(u64 a, u64 b) {
    u64 d; asm("add.rn.f32x2 %0, %1, %2;" : "=l"(d) : "l"(a), "l"(b)); return d;
}
// volatile: smem contents change across tiles under the same address
__device__ __forceinline__ void lds2(u64& a, u64& b, unsigned addr) {
    asm volatile("ld.shared.v2.u64 {%0, %1}, [%2];" : "=l"(a), "=l"(b) : "r"(addr));
}

// ---------------------------------------------------------------------------
// Phase 1: h2[t] = relu(relu(X[t]@W1+b1)@W2+b2). Thread = token.
// j-outer accumulation: per j, one {x,x} pack + 16 broadcast LDS.128 feeding
// 32 FFMA2 into 32 pair-accumulators (64 channels incl. pad).
// ---------------------------------------------------------------------------
__global__ __launch_bounds__(128) void ttcn_phase1(
    const float* __restrict__ X,
    const float* __restrict__ W1, const float* __restrict__ b1,
    const float* __restrict__ W2, const float* __restrict__ b2)
{
    __shared__ __align__(16) float w1p[32 * 64];
    __shared__ __align__(16) float w2p[63 * 64];
    __shared__ __align__(16) float b1p[64];
    __shared__ __align__(16) float b2p[64];

    const int tid = threadIdx.x;
    for (int i = tid; i < 32 * 64; i += 128) {
        int j = i >> 6, c = i & 63;
        w1p[i] = (c < KDIM) ? W1[j * KDIM + c] : 0.0f;
    }
    for (int i = tid; i < 63 * 64; i += 128) {
        int j = i >> 6, c = i & 63;
        w2p[i] = (c < KDIM) ? W2[j * KDIM + c] : 0.0f;
    }
    if (tid < 64) {
        b1p[tid] = (tid < KDIM) ? b1[tid] : 0.0f;
        b2p[tid] = (tid < KDIM) ? b2[tid] : 0.0f;
    }
    __syncthreads();

    const unsigned w1a = (unsigned)__cvta_generic_to_shared(w1p);
    const unsigned w2a = (unsigned)__cvta_generic_to_shared(w2p);
    const unsigned b1a = (unsigned)__cvta_generic_to_shared(b1p);
    const unsigned b2a = (unsigned)__cvta_generic_to_shared(b2p);

    const int t = blockIdx.x * 128 + tid;

    float x[DIN];
    const float4* xp = (const float4*)(X + (size_t)t * DIN);
#pragma unroll
    for (int i = 0; i < DIN / 4; i++) {
        float4 v = xp[i];
        x[4*i+0] = v.x; x[4*i+1] = v.y; x[4*i+2] = v.z; x[4*i+3] = v.w;
    }

    // layer 1
    u64 acc[32];
#pragma unroll
    for (int p = 0; p < 16; p++) lds2(acc[2*p], acc[2*p+1], b1a + 16 * p);
#pragma unroll
    for (int j = 0; j < DIN; j++) {
        const u64 xj = f2pack(x[j], x[j]);
        const unsigned row = w1a + j * 256;
#pragma unroll
        for (int i = 0; i < 16; i++) {
            u64 w0, w1v; lds2(w0, w1v, row + 16 * i);
            acc[2*i]   = fma2(w0,  xj, acc[2*i]);
            acc[2*i+1] = fma2(w1v, xj, acc[2*i+1]);
        }
    }
    float h[64];
#pragma unroll
    for (int p = 0; p < 32; p++) {
        float lo, hi; f2unpack(acc[p], lo, hi);
        h[2*p]   = fmaxf(lo, 0.0f);
        h[2*p+1] = fmaxf(hi, 0.0f);
    }

    // layer 2
    u64 a2[32];
#pragma unroll
    for (int p = 0; p < 16; p++) lds2(a2[2*p], a2[2*p+1], b2a + 16 * p);
#pragma unroll
    for (int j = 0; j < KDIM; j++) {
        const u64 hj = f2pack(h[j], h[j]);
        const unsigned row = w2a + j * 256;
#pragma unroll
        for (int i = 0; i < 16; i++) {
            u64 w0, w1v; lds2(w0, w1v, row + 16 * i);
            a2[2*i]   = fma2(w0,  hj, a2[2*i]);
            a2[2*i+1] = fma2(w1v, hj, a2[2*i+1]);
        }
    }

    float4* o = (float4*)(g_h2 + (size_t)t * 64);
#pragma unroll
    for (int q = 0; q < 16; q++) {
        float l0, h0, l1, h1;
        f2unpack(a2[2*q], l0, h0); f2unpack(a2[2*q+1], l1, h1);
        float4 v;
        v.x = fmaxf(l0, 0.0f); v.y = fmaxf(h0, 0.0f);
        v.z = fmaxf(l1, 0.0f); v.w = fmaxf(h1, 0.0f);
        o[q] = v;   // pad ch 63 = relu(0) = 0 automatically
    }
}

// ---------------------------------------------------------------------------
// Phase 2: fused f = h2@W3+b3, masked online softmax over l, X-weighted pool.
// CTA = (n, 8 k's), 128 threads; warp = 2 k's, lane = d. W3 held in registers
// as f32x2 pairs over j; h-pairs come straight out of LDS.128 -> fma.rn.f32x2.
// ---------------------------------------------------------------------------
__global__ __launch_bounds__(128) void ttcn_phase2(
    const float* __restrict__ X, const float* __restrict__ mask,
    const float* __restrict__ W3, const float* __restrict__ b3,
    const float* __restrict__ Tb, float* __restrict__ out)
{
    const int n   = blockIdx.x;
    const int kb  = blockIdx.y;          // 0..7
    const int tid = threadIdx.x;
    const int d   = tid & 31;
    const int kk  = tid >> 5;            // 0..3
    const int k0  = kb * 8 + kk * 2;
    const int k1  = k0 + 1;
    const bool v0 = (k0 < KDIM);
    const bool v1 = (k1 < KDIM);
    const int c0  = k0 * DIN + d;
    const int c1  = k1 * DIN + d;

    __shared__ __align__(16) float h2s[TL * 64];   // 16 KB
    __shared__ __align__(16) float xs[TL * DIN];   // 8 KB
    __shared__ float ms[TL];

    // W3 columns for both k's, packed over j-pairs (j=63 pad -> 0)
    u64 w0p[32], w1p[32];
#pragma unroll
    for (int p = 0; p < 32; p++) {
        const int j0 = 2 * p, j1 = 2 * p + 1;
        float a0 = v0 ? W3[j0 * CDIM + c0] : 0.0f;
        float a1 = (v0 && j1 < KDIM) ? W3[j1 * CDIM + c0] : 0.0f;
        w0p[p] = f2pack(a0, a1);
        float g0 = v1 ? W3[j0 * CDIM + c1] : 0.0f;
        float g1 = (v1 && j1 < KDIM) ? W3[j1 * CDIM + c1] : 0.0f;
        w1p[p] = f2pack(g0, g1);
    }
    const float b30 = v0 ? b3[c0] : 0.0f;
    const float b31 = v1 ? b3[c1] : 0.0f;

    float m0 = -1e30f, Z0 = 0.0f, S0 = 0.0f;
    float m1 = -1e30f, Z1 = 0.0f, S1 = 0.0f;

    const float4* h2base = (const float4*)(g_h2 + (size_t)n * LX * 64);
    const float4* xbase  = (const float4*)(X + (size_t)n * LX * DIN);
    const float*  mbase  = mask + (size_t)n * LX;
    const unsigned h2sa  = (unsigned)__cvta_generic_to_shared(h2s);

    for (int l0 = 0; l0 < LX; l0 += TL) {
        __syncthreads();
        float4* dh = (float4*)h2s;
#pragma unroll
        for (int i = 0; i < 8; i++)
            dh[tid + 128 * i] = h2base[l0 * 16 + tid + 128 * i];
        float4* dx = (float4*)xs;
#pragma unroll
        for (int i = 0; i < 4; i++)
            dx[tid + 128 * i] = xbase[l0 * 8 + tid + 128 * i];
        if (tid < TL) ms[tid] = mbase[l0 + tid];
        __syncthreads();

        for (int ll = 0; ll < TL; ll++) {
            if (ms[ll] == 0.0f) continue;   // warp-uniform; weight is exactly 0
            const unsigned hrow = h2sa + ll * 256;
            u64 a0 = 0, a1 = 0, g0 = 0, g1 = 0;   // {0f,0f}
#pragma unroll
            for (int i = 0; i < 16; i++) {
                u64 hp0, hp1; lds2(hp0, hp1, hrow + 16 * i);
                a0 = fma2(hp0, w0p[2*i],   a0);
                a1 = fma2(hp1, w0p[2*i+1], a1);
                g0 = fma2(hp0, w1p[2*i],   g0);
                g1 = fma2(hp1, w1p[2*i+1], g1);
            }
            float lo, hi;
            const u64 sa = add2(a0, a1); f2unpack(sa, lo, hi);
            const float f0 = b30 + lo + hi;
            const u64 sg = add2(g0, g1); f2unpack(sg, lo, hi);
            const float f1 = b31 + lo + hi;

            const float xv = xs[ll * DIN + d];

            const float mn0 = fmaxf(m0, f0);
            const float cc0 = __expf(m0 - mn0);
            const float e0  = __expf(f0 - mn0);
            Z0 = fmaf(Z0, cc0, e0);
            S0 = fmaf(S0, cc0, xv * e0);
            m0 = mn0;

            const float mn1 = fmaxf(m1, f1);
            const float cc1 = __expf(m1 - mn1);
            const float e1  = __expf(f1 - mn1);
            Z1 = fmaf(Z1, cc1, e1);
            S1 = fmaf(S1, cc1, xv * e1);
            m1 = mn1;
        }
    }

    float val0 = (v0 && Z0 > 0.0f) ? (S0 / Z0) : 0.0f;
    float val1 = (v1 && Z1 > 0.0f) ? (S1 / Z1) : 0.0f;
#pragma unroll
    for (int off = 16; off; off >>= 1) {
        val0 += __shfl_xor_sync(0xffffffffu, val0, off);
        val1 += __shfl_xor_sync(0xffffffffu, val1, off);
    }
    if (d == 0) {
        if (v0) out[n * KDIM + k0] = fmaxf(val0 + Tb[k0], 0.0f);
        if (v1) out[n * KDIM + k1] = fmaxf(val1 + Tb[k1], 0.0f);
    }
}

extern "C" void kernel_launch(void* const* d_in, const int* in_sizes, int n_in,
                              void* d_out, int out_size) {
    const float* X    = (const float*)d_in[0];
    const float* mask = (const float*)d_in[1];
    const float* W1   = (const float*)d_in[2];
    const float* b1   = (const float*)d_in[3];
    const float* W2   = (const float*)d_in[4];
    const float* b2   = (const float*)d_in[5];
    const float* W3   = (const float*)d_in[6];
    const float* b3   = (const float*)d_in[7];
    const float* Tb   = (const float*)d_in[8];
    float* out = (float*)d_out;

    ttcn_phase1<<<(N_BATCH * LX) / 128, 128>>>(X, W1, b1, W2, b2);
    ttcn_phase2<<<dim3(N_BATCH, 8), 128>>>(X, mask, W3, b3, Tb, out);
}

// round 3
// speedup vs baseline: 1.5634x; 1.1290x over previous
#include <cuda_runtime.h>
#include <cuda_bf16.h>

// Shapes: N=128, LX=512, D=32, K=63, C=K*D=2016
// Inputs: X_int(128,512,32) mask_X(128,512,1) W1(32,63) b1(63)
//         W2(63,63) b2(63) W3(63,2016) b3(2016) T_bias(1,63)
// Output: (128,63) fp32

#define N_BATCH 128
#define LX      512
#define DIN     32
#define KDIM    63
#define CDIM    2016
#define TL      64

typedef unsigned long long u64;

// Compact scratch (live tokens only; rows >= cnt hold stale data, never used)
__device__ __align__(16) float g_h2[(size_t)N_BATCH * LX * 64];   // 16.8 MB
__device__ __align__(16) float g_xc[(size_t)N_BATCH * LX * DIN];  //  8.4 MB
__device__ int   g_cnt[N_BATCH];
__device__ int   g_list[N_BATCH * LX];
__device__ float g_h2max[N_BATCH * 64];
__device__ float g_negb[N_BATCH * CDIM];   // b3[c] - bound[n,c]

// ---- f32x2 helpers --------------------------------------------------------
__device__ __forceinline__ u64 f2pack(float lo, float hi) {
    u64 r; asm("mov.b64 %0, {%1, %2};" : "=l"(r) : "f"(lo), "f"(hi)); return r;
}
__device__ __forceinline__ void f2unpack(u64 v, float& lo, float& hi) {
    asm("mov.b64 {%0, %1}, %2;" : "=f"(lo), "=f"(hi) : "l"(v));
}
__device__ __forceinline__ u64 fma2(u64 a, u64 b, u64 c) {
    u64 d; asm("fma.rn.f32x2 %0, %1, %2, %3;" : "=l"(d) : "l"(a), "l"(b), "l"(c));
    return d;
}
__device__ __forceinline__ u64 add2(u64 a, u64 b) {
    u64 d; asm("add.rn.f32x2 %0, %1, %2;" : "=l"(d) : "l"(a), "l"(b)); return d;
}
__device__ __forceinline__ void lds2(u64& a, u64& b, unsigned addr) {
    asm volatile("ld.shared.v2.u64 {%0, %1}, [%2];" : "=l"(a), "=l"(b) : "r"(addr));
}
__device__ __forceinline__ void cpa16(unsigned dst, const void* src) {
    asm volatile("cp.async.ca.shared.global [%0], [%1], 16;" :: "r"(dst), "l"(src));
}
#define CP_COMMIT() asm volatile("cp.async.commit_group;")
#define CP_WAIT0()  asm volatile("cp.async.wait_group 0;")

// ---------------------------------------------------------------------------
// Kernel A: per-n stream compaction of live token indices.
// ---------------------------------------------------------------------------
__global__ __launch_bounds__(LX) void ttcn_index(const float* __restrict__ mask)
{
    const int n = blockIdx.x, l = threadIdx.x;
    const int lane = l & 31, w = l >> 5;
    const int live = (mask[n * LX + l] != 0.0f);
    const unsigned b = __ballot_sync(0xffffffffu, live);
    __shared__ int wcnt[16];
    if (lane == 0) wcnt[w] = __popc(b);
    __syncthreads();
    int off = 0;
#pragma unroll
    for (int i = 0; i < 16; i++) if (i < w) off += wcnt[i];
    if (live) g_list[n * LX + off + __popc(b & ((1u << lane) - 1))] = l;
    if (l == LX - 1) g_cnt[n] = off + wcnt[15];
}

// ---------------------------------------------------------------------------
// Phase 1 (compact): h2[i] = relu(relu(X[l_i]@W1+b1)@W2+b2) for live tokens,
// plus a compacted copy of X. Thread = live-token slot.
// ---------------------------------------------------------------------------
__global__ __launch_bounds__(128) void ttcn_phase1(
    const float* __restrict__ X,
    const float* __restrict__ W1, const float* __restrict__ b1,
    const float* __restrict__ W2, const float* __restrict__ b2)
{
    __shared__ __align__(16) float w1p[32 * 64];
    __shared__ __align__(16) float w2p[63 * 64];
    __shared__ __align__(16) float b1p[64];
    __shared__ __align__(16) float b2p[64];

    const int tid = threadIdx.x;
    for (int i = tid; i < 32 * 64; i += 128) {
        int j = i >> 6, c = i & 63;
        w1p[i] = (c < KDIM) ? W1[j * KDIM + c] : 0.0f;
    }
    for (int i = tid; i < 63 * 64; i += 128) {
        int j = i >> 6, c = i & 63;
        w2p[i] = (c < KDIM) ? W2[j * KDIM + c] : 0.0f;
    }
    if (tid < 64) {
        b1p[tid] = (tid < KDIM) ? b1[tid] : 0.0f;
        b2p[tid] = (tid < KDIM) ? b2[tid] : 0.0f;
    }
    __syncthreads();

    const int n = blockIdx.x >> 2;
    const int i = ((blockIdx.x & 3) << 7) + tid;   // live slot 0..511
    if (i >= g_cnt[n]) return;
    const int l = g_list[n * LX + i];

    const unsigned w1a = (unsigned)__cvta_generic_to_shared(w1p);
    const unsigned w2a = (unsigned)__cvta_generic_to_shared(w2p);
    const unsigned b1a = (unsigned)__cvta_generic_to_shared(b1p);
    const unsigned b2a = (unsigned)__cvta_generic_to_shared(b2p);

    float x[DIN];
    const float4* xp = (const float4*)(X + ((size_t)n * LX + l) * DIN);
    float4* xo = (float4*)(g_xc + ((size_t)n * LX + i) * DIN);
#pragma unroll
    for (int q = 0; q < DIN / 4; q++) {
        float4 v = xp[q];
        xo[q] = v;
        x[4*q+0] = v.x; x[4*q+1] = v.y; x[4*q+2] = v.z; x[4*q+3] = v.w;
    }

    u64 acc[32];
#pragma unroll
    for (int p = 0; p < 16; p++) lds2(acc[2*p], acc[2*p+1], b1a + 16 * p);
#pragma unroll
    for (int j = 0; j < DIN; j++) {
        const u64 xj = f2pack(x[j], x[j]);
        const unsigned row = w1a + j * 256;
#pragma unroll
        for (int q = 0; q < 16; q++) {
            u64 wa, wb; lds2(wa, wb, row + 16 * q);
            acc[2*q]   = fma2(wa, xj, acc[2*q]);
            acc[2*q+1] = fma2(wb, xj, acc[2*q+1]);
        }
    }
    float h[64];
#pragma unroll
    for (int p = 0; p < 32; p++) {
        float lo, hi; f2unpack(acc[p], lo, hi);
        h[2*p]   = fmaxf(lo, 0.0f);
        h[2*p+1] = fmaxf(hi, 0.0f);
    }

    u64 a2[32];
#pragma unroll
    for (int p = 0; p < 16; p++) lds2(a2[2*p], a2[2*p+1], b2a + 16 * p);
#pragma unroll
    for (int j = 0; j < KDIM; j++) {
        const u64 hj = f2pack(h[j], h[j]);
        const unsigned row = w2a + j * 256;
#pragma unroll
        for (int q = 0; q < 16; q++) {
            u64 wa, wb; lds2(wa, wb, row + 16 * q);
            a2[2*q]   = fma2(wa, hj, a2[2*q]);
            a2[2*q+1] = fma2(wb, hj, a2[2*q+1]);
        }
    }

    float4* o = (float4*)(g_h2 + ((size_t)n * LX + i) * 64);
#pragma unroll
    for (int q = 0; q < 16; q++) {
        float l0, h0, l1, h1;
        f2unpack(a2[2*q], l0, h0); f2unpack(a2[2*q+1], l1, h1);
        float4 v;
        v.x = fmaxf(l0, 0.0f); v.y = fmaxf(h0, 0.0f);
        v.z = fmaxf(l1, 0.0f); v.w = fmaxf(h1, 0.0f);
        o[q] = v;
    }
}

// ---------------------------------------------------------------------------
// Kernel C: h2max[n,j] = max over live slots of h2[n,i,j]  (>= 0)
// ---------------------------------------------------------------------------
__global__ __launch_bounds__(256) void ttcn_h2max()
{
    const int n = blockIdx.x, tid = threadIdx.x;
    const int j = tid & 63, q = tid >> 6;
    const int cnt = g_cnt[n];
    float mx = 0.0f;
    const float* base = g_h2 + (size_t)n * LX * 64 + j;
    for (int i = q; i < cnt; i += 4) mx = fmaxf(mx, base[i * 64]);
    __shared__ float red[256];
    red[tid] = mx;
    __syncthreads();
    if (q == 0)
        g_h2max[n * 64 + j] = fmaxf(fmaxf(red[j], red[64 + j]),
                                    fmaxf(red[128 + j], red[192 + j]));
}

// ---------------------------------------------------------------------------
// Kernel D: negb[n,c] = b3[c] - sum_j |W3[j,c]| * h2max[n,j]
// (upper bound on logit f[n,l,c]; makes exp(f-bound) <= 1, overflow-free)
// ---------------------------------------------------------------------------
__global__ __launch_bounds__(256) void ttcn_bound(
    const float* __restrict__ W3, const float* __restrict__ b3)
{
    const int n = blockIdx.y;
    const int c = blockIdx.x * 256 + threadIdx.x;
    __shared__ float hm[64];
    if (threadIdx.x < 64) hm[threadIdx.x] = g_h2max[n * 64 + threadIdx.x];
    __syncthreads();
    if (c >= CDIM) return;
    float acc = 0.0f;
#pragma unroll 7
    for (int j = 0; j < KDIM; j++)
        acc = fmaf(fabsf(W3[j * CDIM + c]), hm[j], acc);
    g_negb[n * CDIM + c] = b3[c] - acc;
}

// ---------------------------------------------------------------------------
// Phase 2: branchless, bound-shifted softmax pooling over compact tokens.
// CTA = (n, 8 k's), 128 threads; thread = 2 channels; W3 pairs in registers.
// cp.async double-buffered tiles of (h2, xc).
// ---------------------------------------------------------------------------
__global__ __launch_bounds__(128, 3) void ttcn_phase2(
    const float* __restrict__ W3, const float* __restrict__ Tb,
    float* __restrict__ out)
{
    const int n   = blockIdx.x;
    const int kb  = blockIdx.y;
    const int tid = threadIdx.x;
    const int d   = tid & 31;
    const int kk  = tid >> 5;
    const int k0  = kb * 8 + kk * 2;
    const int k1  = k0 + 1;
    const bool v1 = (k1 < KDIM);
    const int c0  = k0 * DIN + d;
    const int c1  = v1 ? (k1 * DIN + d) : c0;

    __shared__ __align__(16) float h2s[2][TL * 64];   // 2 x 16 KB
    __shared__ __align__(16) float xs[2][TL * DIN];   // 2 x 8 KB

    // W3 columns for both k's, packed over j-pairs (j=63 pad -> 0)
    u64 w0p[32], w1p[32];
#pragma unroll
    for (int p = 0; p < 32; p++) {
        const int j0 = 2 * p, j1 = 2 * p + 1;
        float a0 = W3[j0 * CDIM + c0];
        float a1 = (j1 < KDIM) ? W3[j1 * CDIM + c0] : 0.0f;
        w0p[p] = f2pack(a0, a1);
        float g0 = v1 ? W3[j0 * CDIM + c1] : 0.0f;
        float g1 = (v1 && j1 < KDIM) ? W3[j1 * CDIM + c1] : 0.0f;
        w1p[p] = f2pack(g0, g1);
    }
    const float nb0 = g_negb[n * CDIM + c0];
    const float nb1 = v1 ? g_negb[n * CDIM + c1] : 0.0f;

    float Z0 = 0.0f, S0 = 0.0f, Z1 = 0.0f, S1 = 0.0f;

    const int cnt = g_cnt[n];
    const char* h2base = (const char*)(g_h2 + (size_t)n * LX * 64);
    const char* xbase  = (const char*)(g_xc + (size_t)n * LX * DIN);
    const unsigned h2s0 = (unsigned)__cvta_generic_to_shared(&h2s[0][0]);
    const unsigned h2s1 = (unsigned)__cvta_generic_to_shared(&h2s[1][0]);
    const unsigned xs0  = (unsigned)__cvta_generic_to_shared(&xs[0][0]);
    const unsigned xs1  = (unsigned)__cvta_generic_to_shared(&xs[1][0]);

    if (cnt > 0) {
        const int nt = (cnt + TL - 1) / TL;

        // prefetch tile 0 into buffer 0
        {
            const char* hsrc = h2base;
            const char* xsrc = xbase;
#pragma unroll
            for (int q = 0; q < 8; q++)
                cpa16(h2s0 + (tid + 128 * q) * 16, hsrc + (tid + 128 * q) * 16);
#pragma unroll
            for (int q = 0; q < 4; q++)
                cpa16(xs0 + (tid + 128 * q) * 16, xsrc + (tid + 128 * q) * 16);
            CP_COMMIT();
        }

        for (int t = 0; t < nt; t++) {
            CP_WAIT0();
            __syncthreads();
            const int cur = t & 1;
            if (t + 1 < nt) {
                const unsigned hd = cur ? h2s0 : h2s1;
                const unsigned xd = cur ? xs0 : xs1;
                const char* hsrc = h2base + (size_t)(t + 1) * TL * 256;
                const char* xsrc = xbase + (size_t)(t + 1) * TL * 128;
#pragma unroll
                for (int q = 0; q < 8; q++)
                    cpa16(hd + (tid + 128 * q) * 16, hsrc + (tid + 128 * q) * 16);
#pragma unroll
                for (int q = 0; q < 4; q++)
                    cpa16(xd + (tid + 128 * q) * 16, xsrc + (tid + 128 * q) * 16);
                CP_COMMIT();
            }

            const unsigned hrow0 = cur ? h2s1 : h2s0;
            const float* xcur = cur ? &xs[1][0] : &xs[0][0];
            const int tcnt = min(TL, cnt - t * TL);

            for (int ll = 0; ll < tcnt; ll++) {
                const unsigned hrow = hrow0 + ll * 256;
                u64 a0 = 0, a1 = 0, g0 = 0, g1 = 0;
#pragma unroll
                for (int q = 0; q < 16; q++) {
                    u64 hp0, hp1; lds2(hp0, hp1, hrow + 16 * q);
                    a0 = fma2(hp0, w0p[2*q],   a0);
                    a1 = fma2(hp1, w0p[2*q+1], a1);
                    g0 = fma2(hp0, w1p[2*q],   g0);
                    g1 = fma2(hp1, w1p[2*q+1], g1);
                }
                float lo, hi;
                const u64 sa = add2(a0, a1); f2unpack(sa, lo, hi);
                const float f0 = nb0 + lo + hi;
                const u64 sg = add2(g0, g1); f2unpack(sg, lo, hi);
                const float f1 = nb1 + lo + hi;

                const float xv = xcur[ll * DIN + d];
                const float e0 = __expf(f0);      // <= 1 by construction
                const float e1 = __expf(f1);
                Z0 += e0;  S0 = fmaf(xv, e0, S0);
                Z1 += e1;  S1 = fmaf(xv, e1, S1);
            }
            __syncthreads();
        }
    }

    float val0 = (Z0 > 0.0f) ? (S0 / Z0) : 0.0f;
    float val1 = (v1 && Z1 > 0.0f) ? (S1 / Z1) : 0.0f;
#pragma unroll
    for (int off = 16; off; off >>= 1) {
        val0 += __shfl_xor_sync(0xffffffffu, val0, off);
        val1 += __shfl_xor_sync(0xffffffffu, val1, off);
    }
    if (d == 0) {
        out[n * KDIM + k0] = fmaxf(val0 + Tb[k0], 0.0f);
        if (v1) out[n * KDIM + k1] = fmaxf(val1 + Tb[k1], 0.0f);
    }
}

extern "C" void kernel_launch(void* const* d_in, const int* in_sizes, int n_in,
                              void* d_out, int out_size) {
    const float* X    = (const float*)d_in[0];
    const float* mask = (const float*)d_in[1];
    const float* W1   = (const float*)d_in[2];
    const float* b1   = (const float*)d_in[3];
    const float* W2   = (const float*)d_in[4];
    const float* b2   = (const float*)d_in[5];
    const float* W3   = (const float*)d_in[6];
    const float* b3   = (const float*)d_in[7];
    const float* Tb   = (const float*)d_in[8];
    float* out = (float*)d_out;

    ttcn_index<<<N_BATCH, LX>>>(mask);
    ttcn_phase1<<<N_BATCH * 4, 128>>>(X, W1, b1, W2, b2);
    ttcn_h2max<<<N_BATCH, 256>>>();
    ttcn_bound<<<dim3(8, N_BATCH), 256>>>(W3, b3);
    ttcn_phase2<<<dim3(N_BATCH, 8), 128>>>(W3, Tb, out);
}

// round 4
// speedup vs baseline: 1.6275x; 1.0410x over previous
#include <cuda_runtime.h>
#include <cuda_bf16.h>

// Shapes: N=128, LX=512, D=32, K=63, C=K*D=2016
// Inputs: X_int(128,512,32) mask_X(128,512,1) W1(32,63) b1(63)
//         W2(63,63) b2(63) W3(63,2016) b3(2016) T_bias(1,63)
// Output: (128,63) fp32

#define N_BATCH 128
#define LX      512
#define DIN     32
#define KDIM    63
#define CDIM    2016
#define TL      64

typedef unsigned long long u64;

// Scratch (compact over live tokens; rows >= cnt are stale and never read)
__device__ __align__(16) float g_h2[(size_t)N_BATCH * LX * 64];   // 16.8 MB
__device__ __align__(16) float g_xc[(size_t)N_BATCH * LX * DIN];  //  8.4 MB
__device__ int    g_cnt[N_BATCH];
__device__ int    g_list[N_BATCH * LX];
__device__ float  g_h2max[N_BATCH * 64];
__device__ float  g_negb[N_BATCH * CDIM];                  // b3[c] - bound[n,c]
__device__ float2 g_part[2 * N_BATCH * 64 * 32];           // {S, Z} per (half,n,k,d)

// ---- f32x2 helpers --------------------------------------------------------
__device__ __forceinline__ u64 f2pack(float lo, float hi) {
    u64 r; asm("mov.b64 %0, {%1, %2};" : "=l"(r) : "f"(lo), "f"(hi)); return r;
}
__device__ __forceinline__ void f2unpack(u64 v, float& lo, float& hi) {
    asm("mov.b64 {%0, %1}, %2;" : "=f"(lo), "=f"(hi) : "l"(v));
}
__device__ __forceinline__ u64 fma2(u64 a, u64 b, u64 c) {
    u64 d; asm("fma.rn.f32x2 %0, %1, %2, %3;" : "=l"(d) : "l"(a), "l"(b), "l"(c));
    return d;
}
__device__ __forceinline__ u64 add2(u64 a, u64 b) {
    u64 d; asm("add.rn.f32x2 %0, %1, %2;" : "=l"(d) : "l"(a), "l"(b)); return d;
}
// Plain C++ 16B smem load -> LDS.128; scheduler is free to batch/pipeline.
__device__ __forceinline__ void lds_pair(u64& a, u64& b, const float* p) {
    ulonglong2 v = *reinterpret_cast<const ulonglong2*>(p);
    a = v.x; b = v.y;
}
__device__ __forceinline__ void cpa16(unsigned dst, const void* src) {
    asm volatile("cp.async.ca.shared.global [%0], [%1], 16;"
                 :: "r"(dst), "l"(src) : "memory");
}
#define CP_COMMIT() asm volatile("cp.async.commit_group;" ::: "memory")
#define CP_WAIT0()  asm volatile("cp.async.wait_group 0;" ::: "memory")

// ---------------------------------------------------------------------------
// Kernel A: per-n stream compaction of live token indices.
// ---------------------------------------------------------------------------
__global__ __launch_bounds__(LX) void ttcn_index(const float* __restrict__ mask)
{
    const int n = blockIdx.x, l = threadIdx.x;
    const int lane = l & 31, w = l >> 5;
    const int live = (mask[n * LX + l] != 0.0f);
    const unsigned b = __ballot_sync(0xffffffffu, live);
    __shared__ int wcnt[16];
    if (lane == 0) wcnt[w] = __popc(b);
    __syncthreads();
    int off = 0;
#pragma unroll
    for (int i = 0; i < 16; i++) if (i < w) off += wcnt[i];
    if (live) g_list[n * LX + off + __popc(b & ((1u << lane) - 1))] = l;
    if (l == LX - 1) g_cnt[n] = off + wcnt[15];
}

// ---------------------------------------------------------------------------
// Phase 1 (compact): h2[i] = relu(relu(X[l_i]@W1+b1)@W2+b2) for live tokens,
// plus compacted copy of X. Thread = live-token slot.
// ---------------------------------------------------------------------------
__global__ __launch_bounds__(128) void ttcn_phase1(
    const float* __restrict__ X,
    const float* __restrict__ W1, const float* __restrict__ b1,
    const float* __restrict__ W2, const float* __restrict__ b2)
{
    __shared__ __align__(16) float w1p[32 * 64];
    __shared__ __align__(16) float w2p[63 * 64];
    __shared__ __align__(16) float b1p[64];
    __shared__ __align__(16) float b2p[64];

    const int tid = threadIdx.x;
    for (int i = tid; i < 32 * 64; i += 128) {
        int j = i >> 6, c = i & 63;
        w1p[i] = (c < KDIM) ? W1[j * KDIM + c] : 0.0f;
    }
    for (int i = tid; i < 63 * 64; i += 128) {
        int j = i >> 6, c = i & 63;
        w2p[i] = (c < KDIM) ? W2[j * KDIM + c] : 0.0f;
    }
    if (tid < 64) {
        b1p[tid] = (tid < KDIM) ? b1[tid] : 0.0f;
        b2p[tid] = (tid < KDIM) ? b2[tid] : 0.0f;
    }
    __syncthreads();

    const int n = blockIdx.x >> 2;
    const int i = ((blockIdx.x & 3) << 7) + tid;
    if (i >= g_cnt[n]) return;
    const int l = g_list[n * LX + i];

    float x[DIN];
    const float4* xp = (const float4*)(X + ((size_t)n * LX + l) * DIN);
    float4* xo = (float4*)(g_xc + ((size_t)n * LX + i) * DIN);
#pragma unroll
    for (int q = 0; q < DIN / 4; q++) {
        float4 v = xp[q];
        xo[q] = v;
        x[4*q+0] = v.x; x[4*q+1] = v.y; x[4*q+2] = v.z; x[4*q+3] = v.w;
    }

    u64 acc[32];
#pragma unroll
    for (int p = 0; p < 16; p++) lds_pair(acc[2*p], acc[2*p+1], b1p + 4 * p);
#pragma unroll
    for (int j = 0; j < DIN; j++) {
        const u64 xj = f2pack(x[j], x[j]);
        const float* row = w1p + j * 64;
#pragma unroll
        for (int q = 0; q < 16; q++) {
            u64 wa, wb; lds_pair(wa, wb, row + 4 * q);
            acc[2*q]   = fma2(wa, xj, acc[2*q]);
            acc[2*q+1] = fma2(wb, xj, acc[2*q+1]);
        }
    }
    float h[64];
#pragma unroll
    for (int p = 0; p < 32; p++) {
        float lo, hi; f2unpack(acc[p], lo, hi);
        h[2*p]   = fmaxf(lo, 0.0f);
        h[2*p+1] = fmaxf(hi, 0.0f);
    }

    u64 a2[32];
#pragma unroll
    for (int p = 0; p < 16; p++) lds_pair(a2[2*p], a2[2*p+1], b2p + 4 * p);
#pragma unroll
    for (int j = 0; j < KDIM; j++) {
        const u64 hj = f2pack(h[j], h[j]);
        const float* row = w2p + j * 64;
#pragma unroll
        for (int q = 0; q < 16; q++) {
            u64 wa, wb; lds_pair(wa, wb, row + 4 * q);
            a2[2*q]   = fma2(wa, hj, a2[2*q]);
            a2[2*q+1] = fma2(wb, hj, a2[2*q+1]);
        }
    }

    float4* o = (float4*)(g_h2 + ((size_t)n * LX + i) * 64);
#pragma unroll
    for (int q = 0; q < 16; q++) {
        float l0, h0, l1, h1;
        f2unpack(a2[2*q], l0, h0); f2unpack(a2[2*q+1], l1, h1);
        float4 v;
        v.x = fmaxf(l0, 0.0f); v.y = fmaxf(h0, 0.0f);
        v.z = fmaxf(l1, 0.0f); v.w = fmaxf(h1, 0.0f);
        o[q] = v;
    }
}

// ---------------------------------------------------------------------------
// Kernel C: h2max[n,j] = max over live slots of h2[n,i,j]  (>= 0)
// ---------------------------------------------------------------------------
__global__ __launch_bounds__(256) void ttcn_h2max()
{
    const int n = blockIdx.x, tid = threadIdx.x;
    const int j = tid & 63, q = tid >> 6;
    const int cnt = g_cnt[n];
    float mx = 0.0f;
    const float* base = g_h2 + (size_t)n * LX * 64 + j;
    for (int i = q; i < cnt; i += 4) mx = fmaxf(mx, base[i * 64]);
    __shared__ float red[256];
    red[tid] = mx;
    __syncthreads();
    if (q == 0)
        g_h2max[n * 64 + j] = fmaxf(fmaxf(red[j], red[64 + j]),
                                    fmaxf(red[128 + j], red[192 + j]));
}

// ---------------------------------------------------------------------------
// Kernel D: negb[n,c] = b3[c] - sum_j |W3[j,c]| * h2max[n,j]
// ---------------------------------------------------------------------------
__global__ __launch_bounds__(256) void ttcn_bound(
    const float* __restrict__ W3, const float* __restrict__ b3)
{
    const int n = blockIdx.y;
    const int c = blockIdx.x * 256 + threadIdx.x;
    __shared__ float hm[64];
    if (threadIdx.x < 64) hm[threadIdx.x] = g_h2max[n * 64 + threadIdx.x];
    __syncthreads();
    if (c >= CDIM) return;
    float acc = 0.0f;
#pragma unroll 7
    for (int j = 0; j < KDIM; j++)
        acc = fmaf(fabsf(W3[j * CDIM + c]), hm[j], acc);
    g_negb[n * CDIM + c] = b3[c] - acc;
}

// ---------------------------------------------------------------------------
// Phase 2 token body (2 channels per thread)
// ---------------------------------------------------------------------------
struct P2State { float Z0, S0, Z1, S1; };

__device__ __forceinline__ void p2_token(
    const float* __restrict__ hrow, float xv,
    const u64* __restrict__ w0p, const u64* __restrict__ w1p,
    float nb0, float nb1, P2State& st)
{
    u64 a0 = 0, a1 = 0, g0 = 0, g1 = 0;
#pragma unroll
    for (int q = 0; q < 16; q++) {
        u64 hp0, hp1; lds_pair(hp0, hp1, hrow + 4 * q);
        a0 = fma2(hp0, w0p[2*q],   a0);
        a1 = fma2(hp1, w0p[2*q+1], a1);
        g0 = fma2(hp0, w1p[2*q],   g0);
        g1 = fma2(hp1, w1p[2*q+1], g1);
    }
    float lo, hi;
    const u64 sa = add2(a0, a1); f2unpack(sa, lo, hi);
    const float f0 = nb0 + lo + hi;
    const u64 sg = add2(g0, g1); f2unpack(sg, lo, hi);
    const float f1 = nb1 + lo + hi;
    const float e0 = __expf(f0);    // <= 1 by construction of the bound
    const float e1 = __expf(f1);
    st.Z0 += e0;  st.S0 = fmaf(xv, e0, st.S0);
    st.Z1 += e1;  st.S1 = fmaf(xv, e1, st.S1);
}

// ---------------------------------------------------------------------------
// Phase 2: branchless bound-shifted softmax pooling over compact tokens.
// Grid (n, kb, half). CTA = 128 thr, thread = 2 channels. Double-buffered
// cp.async tiles; full tiles use a fixed-64-trip unrolled loop. Per-lane
// (S,Z) partials go to g_part; reduce kernel finishes.
// ---------------------------------------------------------------------------
__global__ __launch_bounds__(128, 3) void ttcn_phase2(
    const float* __restrict__ W3)
{
    const int n   = blockIdx.x;
    const int kb  = blockIdx.y;
    const int z   = blockIdx.z;
    const int tid = threadIdx.x;
    const int d   = tid & 31;
    const int kk  = tid >> 5;
    const int k0  = kb * 8 + kk * 2;
    const int k1  = k0 + 1;
    const bool v1 = (k1 < KDIM);
    const int c0  = k0 * DIN + d;
    const int c1  = v1 ? (k1 * DIN + d) : c0;

    __shared__ __align__(16) float h2s[2][TL * 64];
    __shared__ __align__(16) float xs[2][TL * DIN];

    u64 w0p[32], w1p[32];
#pragma unroll
    for (int p = 0; p < 32; p++) {
        const int j0 = 2 * p, j1 = 2 * p + 1;
        float a0 = W3[j0 * CDIM + c0];
        float a1 = (j1 < KDIM) ? W3[j1 * CDIM + c0] : 0.0f;
        w0p[p] = f2pack(a0, a1);
        float g0 = v1 ? W3[j0 * CDIM + c1] : 0.0f;
        float g1 = (v1 && j1 < KDIM) ? W3[j1 * CDIM + c1] : 0.0f;
        w1p[p] = f2pack(g0, g1);
    }
    const float nb0 = g_negb[n * CDIM + c0];
    const float nb1 = v1 ? g_negb[n * CDIM + c1] : 0.0f;

    P2State st = {0.0f, 0.0f, 0.0f, 0.0f};

    const int cnt = g_cnt[n];
    const int ntt = (cnt + TL - 1) / TL;          // total tiles
    const int ntA = (ntt + 1) >> 1;
    const int t_lo = z ? ntA : 0;
    const int t_hi = z ? ntt : ntA;

    const char* h2base = (const char*)(g_h2 + (size_t)n * LX * 64);
    const char* xbase  = (const char*)(g_xc + (size_t)n * LX * DIN);
    const unsigned h2sa[2] = {
        (unsigned)__cvta_generic_to_shared(&h2s[0][0]),
        (unsigned)__cvta_generic_to_shared(&h2s[1][0]) };
    const unsigned xsa[2] = {
        (unsigned)__cvta_generic_to_shared(&xs[0][0]),
        (unsigned)__cvta_generic_to_shared(&xs[1][0]) };

    if (t_lo < t_hi) {
        // prefetch first tile into buffer 0
        {
            const char* hsrc = h2base + (size_t)t_lo * TL * 256;
            const char* xsrc = xbase + (size_t)t_lo * TL * 128;
#pragma unroll
            for (int q = 0; q < 8; q++)
                cpa16(h2sa[0] + (tid + 128 * q) * 16, hsrc + (tid + 128 * q) * 16);
#pragma unroll
            for (int q = 0; q < 4; q++)
                cpa16(xsa[0] + (tid + 128 * q) * 16, xsrc + (tid + 128 * q) * 16);
            CP_COMMIT();
        }

        for (int t = t_lo; t < t_hi; t++) {
            const int buf = (t - t_lo) & 1;
            CP_WAIT0();
            __syncthreads();
            if (t + 1 < t_hi) {
                const unsigned hd = h2sa[buf ^ 1];
                const unsigned xd = xsa[buf ^ 1];
                const char* hsrc = h2base + (size_t)(t + 1) * TL * 256;
                const char* xsrc = xbase + (size_t)(t + 1) * TL * 128;
#pragma unroll
                for (int q = 0; q < 8; q++)
                    cpa16(hd + (tid + 128 * q) * 16, hsrc + (tid + 128 * q) * 16);
#pragma unroll
                for (int q = 0; q < 4; q++)
                    cpa16(xd + (tid + 128 * q) * 16, xsrc + (tid + 128 * q) * 16);
                CP_COMMIT();
            }

            const float* hb = &h2s[buf][0];
            const float* xb = &xs[buf][0];

            if ((t + 1) * TL <= cnt) {
                // full tile: compile-time trip count
#pragma unroll 4
                for (int ll = 0; ll < TL; ll++)
                    p2_token(hb + ll * 64, xb[ll * DIN + d], w0p, w1p, nb0, nb1, st);
            } else {
                const int tcnt = cnt - t * TL;
                for (int ll = 0; ll < tcnt; ll++)
                    p2_token(hb + ll * 64, xb[ll * DIN + d], w0p, w1p, nb0, nb1, st);
            }
            __syncthreads();
        }
    }

    float2* part = g_part + ((size_t)(z * N_BATCH + n) * 64) * 32;
    part[k0 * 32 + d] = make_float2(st.S0, st.Z0);
    if (v1) part[k1 * 32 + d] = make_float2(st.S1, st.Z1);
}

// ---------------------------------------------------------------------------
// Reduce: combine the two l-halves, divide, reduce over d, bias+relu.
// ---------------------------------------------------------------------------
__global__ __launch_bounds__(256) void ttcn_reduce(
    const float* __restrict__ Tb, float* __restrict__ out)
{
    const int n = blockIdx.x;
    const int d = threadIdx.x & 31;
    const int w = threadIdx.x >> 5;   // 0..7
    const float2* pa = g_part + (size_t)n * 64 * 32;
    const float2* pb = g_part + ((size_t)(N_BATCH + n) * 64) * 32;
#pragma unroll
    for (int kq = 0; kq < 8; kq++) {
        const int k = kq * 8 + w;
        if (k >= KDIM) continue;
        float2 a = pa[k * 32 + d];
        float2 b = pb[k * 32 + d];
        const float S = a.x + b.x, Z = a.y + b.y;
        float val = (Z > 0.0f) ? (S / Z) : 0.0f;
#pragma unroll
        for (int off = 16; off; off >>= 1)
            val += __shfl_xor_sync(0xffffffffu, val, off);
        if (d == 0) out[n * KDIM + k] = fmaxf(val + Tb[k], 0.0f);
    }
}

extern "C" void kernel_launch(void* const* d_in, const int* in_sizes, int n_in,
                              void* d_out, int out_size) {
    const float* X    = (const float*)d_in[0];
    const float* mask = (const float*)d_in[1];
    const float* W1   = (const float*)d_in[2];
    const float* b1   = (const float*)d_in[3];
    const float* W2   = (const float*)d_in[4];
    const float* b2   = (const float*)d_in[5];
    const float* W3   = (const float*)d_in[6];
    const float* b3   = (const float*)d_in[7];
    const float* Tb   = (const float*)d_in[8];
    float* out = (float*)d_out;

    ttcn_index<<<N_BATCH, LX>>>(mask);
    ttcn_phase1<<<N_BATCH * 4, 128>>>(X, W1, b1, W2, b2);
    ttcn_h2max<<<N_BATCH, 256>>>();
    ttcn_bound<<<dim3(8, N_BATCH), 256>>>(W3, b3);
    ttcn_phase2<<<dim3(N_BATCH, 8, 2), 128>>>(W3);
    ttcn_reduce<<<N_BATCH, 256>>>(Tb, out);
}

// round 9
// speedup vs baseline: 2.6710x; 1.6412x over previous
#include <cuda_runtime.h>
#include <cuda_bf16.h>
#include <stdint.h>

// Shapes: N=128, LX=512, D=32, K=63, C=K*D=2016
// Inputs: X_int(128,512,32) mask_X(128,512,1) W1(32,63) b1(63)
//         W2(63,63) b2(63) W3(63,2016) b3(2016) T_bias(1,63)
// Output: (128,63) fp32

#define N_BATCH 128
#define LX      512
#define DIN     32
#define KDIM    63
#define CDIM    2016
#define KSPLIT  192    // [hi | hi | lo] x 64 (pad j=63 -> 0)
#define CH_PAD  2048

typedef unsigned long long u64;

// Scratch
__device__ __align__(16) __nv_bfloat16 g_h2b[(size_t)N_BATCH * LX * KSPLIT]; // 25 MB
__device__ __align__(16) float         g_xc[(size_t)N_BATCH * LX * DIN];    // 8.4 MB
__device__ __align__(16) __nv_bfloat16 g_w3s[(size_t)CH_PAD * KSPLIT];      // 786 KB
__device__ int   g_cnt[N_BATCH];
__device__ int   g_list[N_BATCH * LX];
__device__ int   g_h2max_i[N_BATCH * 64];     // nonneg float bits (atomicMax)
__device__ float g_negb[N_BATCH * CDIM];      // b3[c] - bound[n,c]

// ---- f32x2 helpers --------------------------------------------------------
__device__ __forceinline__ u64 f2pack(float lo, float hi) {
    u64 r; asm("mov.b64 %0, {%1, %2};" : "=l"(r) : "f"(lo), "f"(hi)); return r;
}
__device__ __forceinline__ void f2unpack(u64 v, float& lo, float& hi) {
    asm("mov.b64 {%0, %1}, %2;" : "=f"(lo), "=f"(hi) : "l"(v));
}
__device__ __forceinline__ u64 fma2(u64 a, u64 b, u64 c) {
    u64 d; asm("fma.rn.f32x2 %0, %1, %2, %3;" : "=l"(d) : "l"(a), "l"(b), "l"(c));
    return d;
}
__device__ __forceinline__ void lds_pair(u64& a, u64& b, const float* p) {
    ulonglong2 v = *reinterpret_cast<const ulonglong2*>(p);
    a = v.x; b = v.y;
}

// ---- async / mma plumbing -------------------------------------------------
__device__ __forceinline__ uint32_t smem_u32(const void* p) {
    uint32_t a;
    asm("{ .reg .u64 t; cvta.to.shared.u64 t, %1; cvt.u32.u64 %0, t; }"
        : "=r"(a) : "l"(p));
    return a;
}
__device__ __forceinline__ void cpa16(uint32_t dst, const void* src) {
    asm volatile("cp.async.ca.shared.global [%0], [%1], 16;"
                 :: "r"(dst), "l"(src) : "memory");
}
#define CP_COMMIT() asm volatile("cp.async.commit_group;" ::: "memory")
#define CP_WAIT0()  asm volatile("cp.async.wait_group 0;" ::: "memory")

__device__ __forceinline__ void ldmx4(uint32_t* r, uint32_t addr) {
    asm volatile("ldmatrix.sync.aligned.m8n8.x4.shared.b16 {%0,%1,%2,%3}, [%4];"
                 : "=r"(r[0]), "=r"(r[1]), "=r"(r[2]), "=r"(r[3]) : "r"(addr));
}
__device__ __forceinline__ void mma_bf16(float* c, const uint32_t* a,
                                         uint32_t b0, uint32_t b1) {
    asm volatile(
        "mma.sync.aligned.m16n8k16.row.col.f32.bf16.bf16.f32 "
        "{%0,%1,%2,%3}, {%4,%5,%6,%7}, {%8,%9}, {%0,%1,%2,%3};"
        : "+f"(c[0]), "+f"(c[1]), "+f"(c[2]), "+f"(c[3])
        : "r"(a[0]), "r"(a[1]), "r"(a[2]), "r"(a[3]), "r"(b0), "r"(b1));
}

// ---------------------------------------------------------------------------
// Kernel A: compaction of live token indices + h2max reset.
// ---------------------------------------------------------------------------
__global__ __launch_bounds__(LX) void ttcn_index(const float* __restrict__ mask)
{
    const int n = blockIdx.x, l = threadIdx.x;
    const int lane = l & 31, w = l >> 5;
    if (l < 64) g_h2max_i[n * 64 + l] = 0;
    const int live = (mask[n * LX + l] != 0.0f);
    const unsigned b = __ballot_sync(0xffffffffu, live);
    __shared__ int wcnt[16];
    if (lane == 0) wcnt[w] = __popc(b);
    __syncthreads();
    int off = 0;
#pragma unroll
    for (int i = 0; i < 16; i++) if (i < w) off += wcnt[i];
    if (live) g_list[n * LX + off + __popc(b & ((1u << lane) - 1))] = l;
    if (l == LX - 1) g_cnt[n] = off + wcnt[15];
}

// ---------------------------------------------------------------------------
// Phase 1: per live token, h2 = relu(relu(X@W1+b1)@W2+b2); bf16 split
// [hi|hi|lo] to g_h2b, compact X copy, atomicMax h2max.
// ---------------------------------------------------------------------------
__global__ __launch_bounds__(128) void ttcn_phase1(
    const float* __restrict__ X,
    const float* __restrict__ W1, const float* __restrict__ b1,
    const float* __restrict__ W2, const float* __restrict__ b2)
{
    __shared__ __align__(16) float w1p[32 * 64];
    __shared__ __align__(16) float w2p[63 * 64];
    __shared__ __align__(16) float b1p[64];
    __shared__ __align__(16) float b2p[64];

    const int tid = threadIdx.x;
    for (int i = tid; i < 32 * 64; i += 128) {
        int j = i >> 6, c = i & 63;
        w1p[i] = (c < KDIM) ? W1[j * KDIM + c] : 0.0f;
    }
    for (int i = tid; i < 63 * 64; i += 128) {
        int j = i >> 6, c = i & 63;
        w2p[i] = (c < KDIM) ? W2[j * KDIM + c] : 0.0f;
    }
    if (tid < 64) {
        b1p[tid] = (tid < KDIM) ? b1[tid] : 0.0f;
        b2p[tid] = (tid < KDIM) ? b2[tid] : 0.0f;
    }
    __syncthreads();

    const int n = blockIdx.x >> 2;
    const int i = ((blockIdx.x & 3) << 7) + tid;
    if (i >= g_cnt[n]) return;
    const int l = g_list[n * LX + i];

    float x[DIN];
    const float4* xp = (const float4*)(X + ((size_t)n * LX + l) * DIN);
    float4* xo = (float4*)(g_xc + ((size_t)n * LX + i) * DIN);
#pragma unroll
    for (int q = 0; q < DIN / 4; q++) {
        float4 v = xp[q];
        xo[q] = v;
        x[4*q+0] = v.x; x[4*q+1] = v.y; x[4*q+2] = v.z; x[4*q+3] = v.w;
    }

    u64 acc[32];
#pragma unroll
    for (int p = 0; p < 16; p++) lds_pair(acc[2*p], acc[2*p+1], b1p + 4 * p);
#pragma unroll
    for (int j = 0; j < DIN; j++) {
        const u64 xj = f2pack(x[j], x[j]);
        const float* row = w1p + j * 64;
#pragma unroll
        for (int q = 0; q < 16; q++) {
            u64 wa, wb; lds_pair(wa, wb, row + 4 * q);
            acc[2*q]   = fma2(wa, xj, acc[2*q]);
            acc[2*q+1] = fma2(wb, xj, acc[2*q+1]);
        }
    }
    float h[64];
#pragma unroll
    for (int p = 0; p < 32; p++) {
        float lo, hi; f2unpack(acc[p], lo, hi);
        h[2*p]   = fmaxf(lo, 0.0f);
        h[2*p+1] = fmaxf(hi, 0.0f);
    }

    u64 a2[32];
#pragma unroll
    for (int p = 0; p < 16; p++) lds_pair(a2[2*p], a2[2*p+1], b2p + 4 * p);
#pragma unroll
    for (int j = 0; j < KDIM; j++) {
        const u64 hj = f2pack(h[j], h[j]);
        const float* row = w2p + j * 64;
#pragma unroll
        for (int q = 0; q < 16; q++) {
            u64 wa, wb; lds_pair(wa, wb, row + 4 * q);
            a2[2*q]   = fma2(wa, hj, a2[2*q]);
            a2[2*q+1] = fma2(wb, hj, a2[2*q+1]);
        }
    }

    float v[64];
#pragma unroll
    for (int p = 0; p < 32; p++) {
        float lo, hi; f2unpack(a2[p], lo, hi);
        v[2*p]   = fmaxf(lo, 0.0f);
        v[2*p+1] = fmaxf(hi, 0.0f);
    }

    int* hm = g_h2max_i + n * 64;
#pragma unroll
    for (int j = 0; j < KDIM; j++) atomicMax(hm + j, __float_as_int(v[j]));

    uint32_t hi2[32], lo2[32];
#pragma unroll
    for (int p = 0; p < 32; p++) {
        float v0 = v[2*p], v1 = v[2*p+1];
        __nv_bfloat16 h0 = __float2bfloat16_rn(v0);
        __nv_bfloat16 h1 = __float2bfloat16_rn(v1);
        __nv_bfloat16 l0 = __float2bfloat16_rn(v0 - __bfloat162float(h0));
        __nv_bfloat16 l1 = __float2bfloat16_rn(v1 - __bfloat162float(h1));
        __nv_bfloat162 hp(h0, h1), lp(l0, l1);
        hi2[p] = *reinterpret_cast<uint32_t*>(&hp);
        lo2[p] = *reinterpret_cast<uint32_t*>(&lp);
    }
    uint4* rowp = reinterpret_cast<uint4*>(g_h2b + ((size_t)n * LX + i) * KSPLIT);
#pragma unroll
    for (int q = 0; q < 8; q++) {
        uint4 a = make_uint4(hi2[4*q], hi2[4*q+1], hi2[4*q+2], hi2[4*q+3]);
        uint4 b = make_uint4(lo2[4*q], lo2[4*q+1], lo2[4*q+2], lo2[4*q+3]);
        rowp[q] = a; rowp[8 + q] = a; rowp[16 + q] = b;
    }
}

// ---------------------------------------------------------------------------
// Kernel B: W3split [c, 192] = [Whi | Wlo | Whi] bf16, rows >= 2016 = 0.
// ---------------------------------------------------------------------------
__global__ __launch_bounds__(256) void ttcn_splitw3(const float* __restrict__ W3)
{
    const int i = blockIdx.x * 256 + threadIdx.x;
    const int c = i >> 6, j = i & 63;
    if (c >= CH_PAD) return;
    float v = (c < CDIM && j < KDIM) ? W3[j * CDIM + c] : 0.0f;
    __nv_bfloat16 hi = __float2bfloat16_rn(v);
    __nv_bfloat16 lo = __float2bfloat16_rn(v - __bfloat162float(hi));
    __nv_bfloat16* row = g_w3s + (size_t)c * KSPLIT;
    row[j] = hi; row[64 + j] = lo; row[128 + j] = hi;
}

// ---------------------------------------------------------------------------
// Kernel C: negb[n,c] = b3[c] - sum_j |W3[j,c]| * h2max[n,j]
// ---------------------------------------------------------------------------
__global__ __launch_bounds__(256) void ttcn_bound(
    const float* __restrict__ W3, const float* __restrict__ b3)
{
    const int n = blockIdx.y;
    const int c = blockIdx.x * 256 + threadIdx.x;
    __shared__ float hm[64];
    if (threadIdx.x < 64)
        hm[threadIdx.x] = __int_as_float(g_h2max_i[n * 64 + threadIdx.x]);
    __syncthreads();
    if (c >= CDIM) return;
    float acc = 0.0f;
#pragma unroll 7
    for (int j = 0; j < KDIM; j++)
        acc = fmaf(fabsf(W3[j * CDIM + c]), hm[j], acc);
    g_negb[n * CDIM + c] = b3[c] - acc;
}

// ---------------------------------------------------------------------------
// Phase 2 (mma.sync bf16 split): CTA = (n, 128-channel tile), 4 warps,
// warp = one k (32 channels). F^T tile = W3s[128,192] @ H2s[192, 64 tokens].
// A fragments in registers for whole CTA; B via ldmatrix from padded smem.
// Epilogue on fragments: e = exp(f + negb), Z += e, S += x*e.
// ---------------------------------------------------------------------------
#define AST 400                    // smem row stride bytes (192 bf16 + pad)
#define XST 36                     // x smem row stride floats
#define SM_A 0
#define SM_B (SM_A + 128 * AST)    // 51200
#define SM_X (SM_B + 64 * AST)     // 76800
#define SMEM_TOTAL (SM_X + 64 * XST * 4)   // 86016

__global__ __launch_bounds__(128) void ttcn_p2mma(
    const float* __restrict__ Tb, float* __restrict__ out)
{
    extern __shared__ char smem[];
    const uint32_t sb = smem_u32(smem);
    const int tid  = threadIdx.x;
    const int w    = tid >> 5;
    const int lane = tid & 31;
    const int g    = lane >> 2;     // 0..7 (channel row within 8)
    const int tig  = lane & 3;      // 0..3 (token group)
    const int n  = blockIdx.x;
    const int ct = blockIdx.y;
    const int chbase = ct * 128;

    // --- load A (W3 split channel tile) into smem, then registers ---
    for (int idx = tid; idx < 3072; idx += 128) {
        const int r = idx / 24, chk = idx % 24;
        cpa16(sb + SM_A + r * AST + chk * 16,
              g_w3s + (size_t)(chbase + r) * KSPLIT + chk * 8);
    }
    CP_COMMIT(); CP_WAIT0();
    __syncthreads();

    uint32_t afr[2][12][4];
#pragma unroll
    for (int mr = 0; mr < 2; mr++) {
#pragma unroll
        for (int ks = 0; ks < 12; ks++) {
            const int chl = w * 32 + mr * 16 + (lane & 15);
            const int ko  = ks * 16 + (lane >> 4) * 8;
            ldmx4(afr[mr][ks], sb + SM_A + chl * AST + ko * 2);
        }
    }

    // negb for this thread's 4 channels
    float nbv[2][2];
#pragma unroll
    for (int mr = 0; mr < 2; mr++)
#pragma unroll
        for (int h = 0; h < 2; h++) {
            const int c = chbase + w * 32 + mr * 16 + g + h * 8;
            nbv[mr][h] = (c < CDIM) ? g_negb[n * CDIM + c] : 0.0f;
        }

    const int cnt = g_cnt[n];
    const int ntiles = (cnt + 63) >> 6;
    const float* xs = (const float*)(smem + SM_X);

    float zacc[2][2] = {{0.f, 0.f}, {0.f, 0.f}};
    float sacc[2][2] = {{0.f, 0.f}, {0.f, 0.f}};

    for (int t = 0; t < ntiles; t++) {
        // stage B (64 token split-rows) + X tile
        {
            const __nv_bfloat16* bsrc = g_h2b + ((size_t)n * LX + t * 64) * KSPLIT;
            for (int idx = tid; idx < 1536; idx += 128) {
                const int r = idx / 24, chk = idx % 24;
                cpa16(sb + SM_B + r * AST + chk * 16, bsrc + r * KSPLIT + chk * 8);
            }
            const float* xsrc = g_xc + ((size_t)n * LX + t * 64) * DIN;
            for (int idx = tid; idx < 512; idx += 128) {
                const int r = idx >> 3, q = idx & 7;
                cpa16(sb + SM_X + r * XST * 4 + q * 16, xsrc + r * DIN + q * 4);
            }
            CP_COMMIT(); CP_WAIT0();
        }
        __syncthreads();

        for (int nbp = 0; nbp < 4; nbp++) {
            float ac[2][2][4];
#pragma unroll
            for (int mr = 0; mr < 2; mr++)
#pragma unroll
                for (int nb = 0; nb < 2; nb++)
#pragma unroll
                    for (int q = 0; q < 4; q++) ac[mr][nb][q] = 0.0f;

#pragma unroll
            for (int ks = 0; ks < 12; ks++) {
                uint32_t bf[4];
                const int tokl = nbp * 16 + (lane & 7) + ((lane >> 4) << 3);
                const int ko   = ks * 16 + ((lane >> 3) & 1) * 8;
                ldmx4(bf, sb + SM_B + tokl * AST + ko * 2);
                mma_bf16(ac[0][0], afr[0][ks], bf[0], bf[1]);
                mma_bf16(ac[1][0], afr[1][ks], bf[0], bf[1]);
                mma_bf16(ac[0][1], afr[0][ks], bf[2], bf[3]);
                mma_bf16(ac[1][1], afr[1][ks], bf[2], bf[3]);
            }

            // epilogue on fragments
#pragma unroll
            for (int mr = 0; mr < 2; mr++) {
#pragma unroll
                for (int nb = 0; nb < 2; nb++) {
                    const int tl0 = nbp * 16 + nb * 8 + 2 * tig;
                    const int gt0 = t * 64 + tl0;
                    const int dA = mr * 16 + g, dB = dA + 8;
                    const float* x0 = xs + tl0 * XST;
                    float eA0 = __expf(ac[mr][nb][0] + nbv[mr][0]);
                    float eA1 = __expf(ac[mr][nb][1] + nbv[mr][0]);
                    float eB0 = __expf(ac[mr][nb][2] + nbv[mr][1]);
                    float eB1 = __expf(ac[mr][nb][3] + nbv[mr][1]);
                    const bool v0 = gt0 < cnt, v1 = gt0 + 1 < cnt;
                    eA0 = v0 ? eA0 : 0.0f;  eA1 = v1 ? eA1 : 0.0f;
                    eB0 = v0 ? eB0 : 0.0f;  eB1 = v1 ? eB1 : 0.0f;
                    zacc[mr][0] += eA0 + eA1;
                    sacc[mr][0] += x0[dA] * eA0 + x0[XST + dA] * eA1;
                    zacc[mr][1] += eB0 + eB1;
                    sacc[mr][1] += x0[dB] * eB0 + x0[XST + dB] * eB1;
                }
            }
        }
        __syncthreads();
    }

    // reduce over the 4-lane token group, then sum 32 channels per warp
    float val = 0.0f;
#pragma unroll
    for (int mr = 0; mr < 2; mr++)
#pragma unroll
        for (int h = 0; h < 2; h++) {
            float z = zacc[mr][h], s = sacc[mr][h];
            z += __shfl_xor_sync(0xffffffffu, z, 1);
            z += __shfl_xor_sync(0xffffffffu, z, 2);
            s += __shfl_xor_sync(0xffffffffu, s, 1);
            s += __shfl_xor_sync(0xffffffffu, s, 2);
            val += (z > 0.0f) ? (s / z) : 0.0f;
        }
    val = (tig == 0) ? val : 0.0f;
#pragma unroll
    for (int off = 16; off; off >>= 1)
        val += __shfl_xor_sync(0xffffffffu, val, off);

    const int k = ct * 4 + w;
    if (lane == 0 && k < KDIM)
        out[n * KDIM + k] = fmaxf(val + Tb[k], 0.0f);
}

extern "C" void kernel_launch(void* const* d_in, const int* in_sizes, int n_in,
                              void* d_out, int out_size) {
    const float* X    = (const float*)d_in[0];
    const float* mask = (const float*)d_in[1];
    const float* W1   = (const float*)d_in[2];
    const float* b1   = (const float*)d_in[3];
    const float* W2   = (const float*)d_in[4];
    const float* b2   = (const float*)d_in[5];
    const float* W3   = (const float*)d_in[6];
    const float* b3   = (const float*)d_in[7];
    const float* Tb   = (const float*)d_in[8];
    float* out = (float*)d_out;

    cudaFuncSetAttribute(ttcn_p2mma,
                         cudaFuncAttributeMaxDynamicSharedMemorySize, SMEM_TOTAL);

    ttcn_index<<<N_BATCH, LX>>>(mask);
    ttcn_phase1<<<N_BATCH * 4, 128>>>(X, W1, b1, W2, b2);
    ttcn_splitw3<<<(CH_PAD * 64) / 256, 256>>>(W3);
    ttcn_bound<<<dim3(8, N_BATCH), 256>>>(W3, b3);
    ttcn_p2mma<<<dim3(N_BATCH, 16), 128, SMEM_TOTAL>>>(Tb, out);
}

// round 11
// speedup vs baseline: 2.7556x; 1.0317x over previous
#include <cuda_runtime.h>
#include <cuda_bf16.h>
#include <stdint.h>

// Shapes: N=128, LX=512, D=32, K=63, C=K*D=2016
// Inputs: X_int(128,512,32) mask_X(128,512,1) W1(32,63) b1(63)
//         W2(63,63) b2(63) W3(63,2016) b3(2016) T_bias(1,63)
// Output: (128,63) fp32

#define N_BATCH 128
#define LX      512
#define DIN     32
#define KDIM    63
#define CDIM    2016
#define KSPLIT  192    // [hi | hi | lo] x 64 (pad j=63 -> 0)
#define CH_PAD  2048

typedef unsigned long long u64;

// Scratch
__device__ __align__(16) __nv_bfloat16 g_h2b[(size_t)N_BATCH * LX * KSPLIT]; // 25 MB
__device__ __align__(16) float         g_xc[(size_t)N_BATCH * LX * DIN];    // 8.4 MB
__device__ __align__(16) __nv_bfloat16 g_w3s[(size_t)CH_PAD * KSPLIT];      // 786 KB
__device__ int   g_cnt[N_BATCH];
__device__ int   g_list[N_BATCH * LX];
__device__ int   g_h2max_i[N_BATCH * 64];     // nonneg float bits (atomicMax)
__device__ float g_negb[N_BATCH * CDIM];      // b3[c] - bound[n,c]

// ---- f32x2 helpers --------------------------------------------------------
__device__ __forceinline__ u64 f2pack(float lo, float hi) {
    u64 r; asm("mov.b64 %0, {%1, %2};" : "=l"(r) : "f"(lo), "f"(hi)); return r;
}
__device__ __forceinline__ void f2unpack(u64 v, float& lo, float& hi) {
    asm("mov.b64 {%0, %1}, %2;" : "=f"(lo), "=f"(hi) : "l"(v));
}
__device__ __forceinline__ u64 fma2(u64 a, u64 b, u64 c) {
    u64 d; asm("fma.rn.f32x2 %0, %1, %2, %3;" : "=l"(d) : "l"(a), "l"(b), "l"(c));
    return d;
}
__device__ __forceinline__ void lds_pair(u64& a, u64& b, const float* p) {
    ulonglong2 v = *reinterpret_cast<const ulonglong2*>(p);
    a = v.x; b = v.y;
}

// ---- async / mma plumbing -------------------------------------------------
__device__ __forceinline__ uint32_t smem_u32(const void* p) {
    uint32_t a;
    asm("{ .reg .u64 t; cvta.to.shared.u64 t, %1; cvt.u32.u64 %0, t; }"
        : "=r"(a) : "l"(p));
    return a;
}
__device__ __forceinline__ void cpa16(uint32_t dst, const void* src) {
    asm volatile("cp.async.ca.shared.global [%0], [%1], 16;"
                 :: "r"(dst), "l"(src) : "memory");
}
#define CP_COMMIT() asm volatile("cp.async.commit_group;" ::: "memory")
#define CP_WAIT0()  asm volatile("cp.async.wait_group 0;" ::: "memory")
#define CP_WAIT1()  asm volatile("cp.async.wait_group 1;" ::: "memory")

__device__ __forceinline__ void ldmx4(uint32_t* r, uint32_t addr) {
    asm volatile("ldmatrix.sync.aligned.m8n8.x4.shared.b16 {%0,%1,%2,%3}, [%4];"
                 : "=r"(r[0]), "=r"(r[1]), "=r"(r[2]), "=r"(r[3]) : "r"(addr));
}
__device__ __forceinline__ void mma_bf16(float* c, const uint32_t* a,
                                         uint32_t b0, uint32_t b1) {
    asm volatile(
        "mma.sync.aligned.m16n8k16.row.col.f32.bf16.bf16.f32 "
        "{%0,%1,%2,%3}, {%4,%5,%6,%7}, {%8,%9}, {%0,%1,%2,%3};"
        : "+f"(c[0]), "+f"(c[1]), "+f"(c[2]), "+f"(c[3])
        : "r"(a[0]), "r"(a[1]), "r"(a[2]), "r"(a[3]), "r"(b0), "r"(b1));
}

// ---------------------------------------------------------------------------
// Kernel A: compaction of live token indices + h2max reset.
// ---------------------------------------------------------------------------
__global__ __launch_bounds__(LX) void ttcn_index(const float* __restrict__ mask)
{
    const int n = blockIdx.x, l = threadIdx.x;
    const int lane = l & 31, w = l >> 5;
    if (l < 64) g_h2max_i[n * 64 + l] = 0;
    const int live = (mask[n * LX + l] != 0.0f);
    const unsigned b = __ballot_sync(0xffffffffu, live);
    __shared__ int wcnt[16];
    if (lane == 0) wcnt[w] = __popc(b);
    __syncthreads();
    int off = 0;
#pragma unroll
    for (int i = 0; i < 16; i++) if (i < w) off += wcnt[i];
    if (live) g_list[n * LX + off + __popc(b & ((1u << lane) - 1))] = l;
    if (l == LX - 1) g_cnt[n] = off + wcnt[15];
}

// ---------------------------------------------------------------------------
// Phase 1: per live token, h2 = relu(relu(X@W1+b1)@W2+b2); bf16 split
// [hi|hi|lo] to g_h2b, compact X copy, atomicMax h2max.
// ---------------------------------------------------------------------------
__global__ __launch_bounds__(128) void ttcn_phase1(
    const float* __restrict__ X,
    const float* __restrict__ W1, const float* __restrict__ b1,
    const float* __restrict__ W2, const float* __restrict__ b2)
{
    __shared__ __align__(16) float w1p[32 * 64];
    __shared__ __align__(16) float w2p[63 * 64];
    __shared__ __align__(16) float b1p[64];
    __shared__ __align__(16) float b2p[64];

    const int tid = threadIdx.x;
    for (int i = tid; i < 32 * 64; i += 128) {
        int j = i >> 6, c = i & 63;
        w1p[i] = (c < KDIM) ? W1[j * KDIM + c] : 0.0f;
    }
    for (int i = tid; i < 63 * 64; i += 128) {
        int j = i >> 6, c = i & 63;
        w2p[i] = (c < KDIM) ? W2[j * KDIM + c] : 0.0f;
    }
    if (tid < 64) {
        b1p[tid] = (tid < KDIM) ? b1[tid] : 0.0f;
        b2p[tid] = (tid < KDIM) ? b2[tid] : 0.0f;
    }
    __syncthreads();

    const int n = blockIdx.x >> 2;
    const int i = ((blockIdx.x & 3) << 7) + tid;
    if (i >= g_cnt[n]) return;
    const int l = g_list[n * LX + i];

    float x[DIN];
    const float4* xp = (const float4*)(X + ((size_t)n * LX + l) * DIN);
    float4* xo = (float4*)(g_xc + ((size_t)n * LX + i) * DIN);
#pragma unroll
    for (int q = 0; q < DIN / 4; q++) {
        float4 v = xp[q];
        xo[q] = v;
        x[4*q+0] = v.x; x[4*q+1] = v.y; x[4*q+2] = v.z; x[4*q+3] = v.w;
    }

    u64 acc[32];
#pragma unroll
    for (int p = 0; p < 16; p++) lds_pair(acc[2*p], acc[2*p+1], b1p + 4 * p);
#pragma unroll
    for (int j = 0; j < DIN; j++) {
        const u64 xj = f2pack(x[j], x[j]);
        const float* row = w1p + j * 64;
#pragma unroll
        for (int q = 0; q < 16; q++) {
            u64 wa, wb; lds_pair(wa, wb, row + 4 * q);
            acc[2*q]   = fma2(wa, xj, acc[2*q]);
            acc[2*q+1] = fma2(wb, xj, acc[2*q+1]);
        }
    }
    float h[64];
#pragma unroll
    for (int p = 0; p < 32; p++) {
        float lo, hi; f2unpack(acc[p], lo, hi);
        h[2*p]   = fmaxf(lo, 0.0f);
        h[2*p+1] = fmaxf(hi, 0.0f);
    }

    u64 a2[32];
#pragma unroll
    for (int p = 0; p < 16; p++) lds_pair(a2[2*p], a2[2*p+1], b2p + 4 * p);
#pragma unroll
    for (int j = 0; j < KDIM; j++) {
        const u64 hj = f2pack(h[j], h[j]);
        const float* row = w2p + j * 64;
#pragma unroll
        for (int q = 0; q < 16; q++) {
            u64 wa, wb; lds_pair(wa, wb, row + 4 * q);
            a2[2*q]   = fma2(wa, hj, a2[2*q]);
            a2[2*q+1] = fma2(wb, hj, a2[2*q+1]);
        }
    }

    float v[64];
#pragma unroll
    for (int p = 0; p < 32; p++) {
        float lo, hi; f2unpack(a2[p], lo, hi);
        v[2*p]   = fmaxf(lo, 0.0f);
        v[2*p+1] = fmaxf(hi, 0.0f);
    }

    int* hm = g_h2max_i + n * 64;
#pragma unroll
    for (int j = 0; j < KDIM; j++) atomicMax(hm + j, __float_as_int(v[j]));

    uint32_t hi2[32], lo2[32];
#pragma unroll
    for (int p = 0; p < 32; p++) {
        float v0 = v[2*p], v1 = v[2*p+1];
        __nv_bfloat16 h0 = __float2bfloat16_rn(v0);
        __nv_bfloat16 h1 = __float2bfloat16_rn(v1);
        __nv_bfloat16 l0 = __float2bfloat16_rn(v0 - __bfloat162float(h0));
        __nv_bfloat16 l1 = __float2bfloat16_rn(v1 - __bfloat162float(h1));
        __nv_bfloat162 hp(h0, h1), lp(l0, l1);
        hi2[p] = *reinterpret_cast<uint32_t*>(&hp);
        lo2[p] = *reinterpret_cast<uint32_t*>(&lp);
    }
    uint4* rowp = reinterpret_cast<uint4*>(g_h2b + ((size_t)n * LX + i) * KSPLIT);
#pragma unroll
    for (int q = 0; q < 8; q++) {
        uint4 a = make_uint4(hi2[4*q], hi2[4*q+1], hi2[4*q+2], hi2[4*q+3]);
        uint4 b = make_uint4(lo2[4*q], lo2[4*q+1], lo2[4*q+2], lo2[4*q+3]);
        rowp[q] = a; rowp[8 + q] = a; rowp[16 + q] = b;
    }
}

// ---------------------------------------------------------------------------
// Kernel B: W3split [c, 192] = [Whi | Wlo | Whi] bf16, rows >= 2016 = 0.
// ---------------------------------------------------------------------------
__global__ __launch_bounds__(256) void ttcn_splitw3(const float* __restrict__ W3)
{
    const int i = blockIdx.x * 256 + threadIdx.x;
    const int c = i >> 6, j = i & 63;
    if (c >= CH_PAD) return;
    float v = (c < CDIM && j < KDIM) ? W3[j * CDIM + c] : 0.0f;
    __nv_bfloat16 hi = __float2bfloat16_rn(v);
    __nv_bfloat16 lo = __float2bfloat16_rn(v - __bfloat162float(hi));
    __nv_bfloat16* row = g_w3s + (size_t)c * KSPLIT;
    row[j] = hi; row[64 + j] = lo; row[128 + j] = hi;
}

// ---------------------------------------------------------------------------
// Kernel C: negb[n,c] = b3[c] - sum_j |W3[j,c]| * h2max[n,j]
// W3 column |w| in registers, 32 n's per CTA with h2max in smem ->
// W3 read 4x total instead of 128x, pure-FMA inner loop.
// ---------------------------------------------------------------------------
__global__ __launch_bounds__(128) void ttcn_bound(
    const float* __restrict__ W3, const float* __restrict__ b3)
{
    const int c  = blockIdx.x * 128 + threadIdx.x;
    const int n0 = blockIdx.y * 32;
    __shared__ float hm[32 * 64];
    for (int i = threadIdx.x; i < 32 * 64; i += 128)
        hm[i] = __int_as_float(g_h2max_i[n0 * 64 + i]);
    __syncthreads();
    if (c >= CDIM) return;
    float w[KDIM];
#pragma unroll
    for (int j = 0; j < KDIM; j++) w[j] = fabsf(W3[j * CDIM + c]);
    const float bb = b3[c];
    for (int nn = 0; nn < 32; nn++) {
        float acc = 0.0f;
        const float* h = hm + nn * 64;
#pragma unroll
        for (int j = 0; j < KDIM; j++) acc = fmaf(w[j], h[j], acc);
        g_negb[(n0 + nn) * CDIM + c] = bb - acc;
    }
}

// ---------------------------------------------------------------------------
// Phase 2 (mma.sync bf16 split): CTA = (n, 128-channel tile), 4 warps,
// warp = one k (32 channels). F^T tile = W3s[128,192] @ H2s[192, 64 tokens].
// A fragments in registers; A's smem region is reused as two B+X buffers
// (double-buffered cp.async pipeline, wait_group 1).
// ---------------------------------------------------------------------------
#define AST 400                    // smem row stride bytes (192 bf16 + pad)
#define XST 36                     // x smem row stride floats
#define XOFF (64 * AST)            // 25600: X offset within a buffer
#define BUF_SZ (XOFF + 64 * XST * 4)   // 34816
#define SMEM_TOTAL (2 * BUF_SZ)    // 69632 (>= A tile 128*AST = 51200)

__global__ __launch_bounds__(128) void ttcn_p2mma(
    const float* __restrict__ Tb, float* __restrict__ out)
{
    extern __shared__ char smem[];
    const uint32_t sb = smem_u32(smem);
    const int tid  = threadIdx.x;
    const int w    = tid >> 5;
    const int lane = tid & 31;
    const int g    = lane >> 2;     // 0..7 (channel row within 8)
    const int tig  = lane & 3;      // 0..3 (token group)
    const int n  = blockIdx.x;
    const int ct = blockIdx.y;
    const int chbase = ct * 128;

    // --- load A (W3 split channel tile) into smem (offset 0), then regs ---
    for (int idx = tid; idx < 3072; idx += 128) {
        const int r = idx / 24, chk = idx % 24;
        cpa16(sb + r * AST + chk * 16,
              g_w3s + (size_t)(chbase + r) * KSPLIT + chk * 8);
    }
    CP_COMMIT(); CP_WAIT0();
    __syncthreads();

    uint32_t afr[2][12][4];
#pragma unroll
    for (int mr = 0; mr < 2; mr++) {
#pragma unroll
        for (int ks = 0; ks < 12; ks++) {
            const int chl = w * 32 + mr * 16 + (lane & 15);
            const int ko  = ks * 16 + (lane >> 4) * 8;
            ldmx4(afr[mr][ks], sb + chl * AST + ko * 2);
        }
    }
    __syncthreads();   // A fully consumed; smem free for B/X buffers

    // negb for this thread's 4 channels
    float nbv[2][2];
#pragma unroll
    for (int mr = 0; mr < 2; mr++)
#pragma unroll
        for (int h = 0; h < 2; h++) {
            const int c = chbase + w * 32 + mr * 16 + g + h * 8;
            nbv[mr][h] = (c < CDIM) ? g_negb[n * CDIM + c] : 0.0f;
        }

    const int cnt = g_cnt[n];
    const int ntiles = (cnt + 63) >> 6;
    const char* h2base = (const char*)(g_h2b + (size_t)n * LX * KSPLIT);
    const char* xbase  = (const char*)(g_xc + (size_t)n * LX * DIN);

    // stage tile tt into buffer at base bb (B rows + X tile)
    auto stage = [&](int tt, uint32_t bb) {
        const char* bsrc = h2base + (size_t)tt * 64 * (KSPLIT * 2);
        for (int idx = tid; idx < 1536; idx += 128) {
            const int r = idx / 24, chk = idx % 24;
            cpa16(bb + r * AST + chk * 16, bsrc + r * (KSPLIT * 2) + chk * 16);
        }
        const char* xsrc = xbase + (size_t)tt * 64 * (DIN * 4);
        for (int idx = tid; idx < 512; idx += 128) {
            const int r = idx >> 3, q = idx & 7;
            cpa16(bb + XOFF + r * (XST * 4) + q * 16, xsrc + r * (DIN * 4) + q * 16);
        }
        CP_COMMIT();
    };

    float zacc[2][2] = {{0.f, 0.f}, {0.f, 0.f}};
    float sacc[2][2] = {{0.f, 0.f}, {0.f, 0.f}};

    if (ntiles > 0) stage(0, sb);
    if (ntiles > 1) stage(1, sb + BUF_SZ);

    for (int t = 0; t < ntiles; t++) {
        const uint32_t bufb = sb + ((t & 1) ? BUF_SZ : 0);
        if (t + 1 < ntiles) { CP_WAIT1(); } else { CP_WAIT0(); }
        __syncthreads();

        const float* xs = (const float*)(smem + ((t & 1) ? BUF_SZ : 0) + XOFF);

        for (int nbp = 0; nbp < 4; nbp++) {
            float ac[2][2][4];
#pragma unroll
            for (int mr = 0; mr < 2; mr++)
#pragma unroll
                for (int nb = 0; nb < 2; nb++)
#pragma unroll
                    for (int q = 0; q < 4; q++) ac[mr][nb][q] = 0.0f;

#pragma unroll
            for (int ks = 0; ks < 12; ks++) {
                uint32_t bf[4];
                const int tokl = nbp * 16 + (lane & 7) + ((lane >> 4) << 3);
                const int ko   = ks * 16 + ((lane >> 3) & 1) * 8;
                ldmx4(bf, bufb + tokl * AST + ko * 2);
                mma_bf16(ac[0][0], afr[0][ks], bf[0], bf[1]);
                mma_bf16(ac[1][0], afr[1][ks], bf[0], bf[1]);
                mma_bf16(ac[0][1], afr[0][ks], bf[2], bf[3]);
                mma_bf16(ac[1][1], afr[1][ks], bf[2], bf[3]);
            }

            // epilogue on fragments
#pragma unroll
            for (int mr = 0; mr < 2; mr++) {
#pragma unroll
                for (int nb = 0; nb < 2; nb++) {
                    const int tl0 = nbp * 16 + nb * 8 + 2 * tig;
                    const int gt0 = t * 64 + tl0;
                    const int dA = mr * 16 + g, dB = dA + 8;
                    const float* x0 = xs + tl0 * XST;
                    float eA0 = __expf(ac[mr][nb][0] + nbv[mr][0]);
                    float eA1 = __expf(ac[mr][nb][1] + nbv[mr][0]);
                    float eB0 = __expf(ac[mr][nb][2] + nbv[mr][1]);
                    float eB1 = __expf(ac[mr][nb][3] + nbv[mr][1]);
                    const bool v0 = gt0 < cnt, v1 = gt0 + 1 < cnt;
                    eA0 = v0 ? eA0 : 0.0f;  eA1 = v1 ? eA1 : 0.0f;
                    eB0 = v0 ? eB0 : 0.0f;  eB1 = v1 ? eB1 : 0.0f;
                    zacc[mr][0] += eA0 + eA1;
                    sacc[mr][0] += x0[dA] * eA0 + x0[XST + dA] * eA1;
                    zacc[mr][1] += eB0 + eB1;
                    sacc[mr][1] += x0[dB] * eB0 + x0[XST + dB] * eB1;
                }
            }
        }
        __syncthreads();
        if (t + 2 < ntiles) stage(t + 2, bufb);
    }

    // reduce over the 4-lane token group, then sum 32 channels per warp
    float val = 0.0f;
#pragma unroll
    for (int mr = 0; mr < 2; mr++)
#pragma unroll
        for (int h = 0; h < 2; h++) {
            float z = zacc[mr][h], s = sacc[mr][h];
            z += __shfl_xor_sync(0xffffffffu, z, 1);
            z += __shfl_xor_sync(0xffffffffu, z, 2);
            s += __shfl_xor_sync(0xffffffffu, s, 1);
            s += __shfl_xor_sync(0xffffffffu, s, 2);
            val += (z > 0.0f) ? (s / z) : 0.0f;
        }
    val = (tig == 0) ? val : 0.0f;
#pragma unroll
    for (int off = 16; off; off >>= 1)
        val += __shfl_xor_sync(0xffffffffu, val, off);

    const int k = ct * 4 + w;
    if (lane == 0 && k < KDIM)
        out[n * KDIM + k] = fmaxf(val + Tb[k], 0.0f);
}

extern "C" void kernel_launch(void* const* d_in, const int* in_sizes, int n_in,
                              void* d_out, int out_size) {
    const float* X    = (const float*)d_in[0];
    const float* mask = (const float*)d_in[1];
    const float* W1   = (const float*)d_in[2];
    const float* b1   = (const float*)d_in[3];
    const float* W2   = (const float*)d_in[4];
    const float* b2   = (const float*)d_in[5];
    const float* W3   = (const float*)d_in[6];
    const float* b3   = (const float*)d_in[7];
    const float* Tb   = (const float*)d_in[8];
    float* out = (float*)d_out;

    cudaFuncSetAttribute(ttcn_p2mma,
                         cudaFuncAttributeMaxDynamicSharedMemorySize, SMEM_TOTAL);

    ttcn_index<<<N_BATCH, LX>>>(mask);
    ttcn_phase1<<<N_BATCH * 4, 128>>>(X, W1, b1, W2, b2);
    ttcn_splitw3<<<(CH_PAD * 64) / 256, 256>>>(W3);
    ttcn_bound<<<dim3(16, 4), 128>>>(W3, b3);
    ttcn_p2mma<<<dim3(N_BATCH, 16), 128, SMEM_TOTAL>>>(Tb, out);
}